// round 14
// baseline (speedup 1.0000x reference)
#include <cuda_runtime.h>
#include <cuda_fp16.h>
#include <math.h>

#define N_NODES 100000
#define N_EDGES 3200000
#define D 64
#define NEG_SLOPE 0.01f
#define NTILES ((N_NODES + 255) / 256)   // 391

#define NPB 64           // nodes per fused block
#define TPB 512          // 8 threads/node (gather); 16 warps (mma)
#define AB_STRIDE_H 136  // halves per ab row (272B: conflict-free rotation)
#define W_STRIDE_H 72    // halves per weight row (144B: same rotation)
#define SMEM_AB_BYTES (NPB * AB_STRIDE_H * 2)        // 17408
#define SMEM_W_BYTES  (128 * W_STRIDE_H * 2)         // 18432
#define SMEM_BYTES    (SMEM_AB_BYTES + SMEM_W_BYTES) // 35840

// ---------------- device scratch (no allocations allowed) ----------------
__device__ __half g_xh [N_NODES * D];   // fp16 x
__device__ __half g_hAh[N_NODES * D];   // fp16 h1
__device__ __half g_hBh[N_NODES * D];   // fp16 h2
__device__ __half g_w16[2][8192];       // fp16 weights: [layerSel][k*64+n]
__device__ float  g_rsq[N_NODES];
__device__ int    g_deg[N_NODES];
__device__ int    g_off[N_NODES + 1];
__device__ int    g_cur[N_NODES];
__device__ int2   g_edge[N_EDGES];      // {src, bitcast(w)} grouped by dst
__device__ int                g_ticket;
__device__ unsigned long long g_state[NTILES];

// ---------------- precompute kernels (unchanged, known-good) -------------
__global__ void k_count(const int* __restrict__ dst) {
    int e = blockIdx.x * blockDim.x + threadIdx.x;
    if (e < N_EDGES) atomicAdd(&g_deg[dst[e]], 1);
}

__global__ void __launch_bounds__(256) k_scan() {
    __shared__ int sh[256];
    __shared__ int s_tile, s_excl;
    int tid = threadIdx.x;
    if (tid == 0) s_tile = atomicAdd(&g_ticket, 1);
    __syncthreads();
    int tile = s_tile;
    int i = tile * 256 + tid;
    int deg = (i < N_NODES) ? g_deg[i] : 0;
    int val = deg;
    sh[tid] = val;
    __syncthreads();
    for (int ofs = 1; ofs < 256; ofs <<= 1) {
        int t = (tid >= ofs) ? sh[tid - ofs] : 0;
        __syncthreads();
        val += t;
        sh[tid] = val;
        __syncthreads();
    }
    int total = sh[255];

    volatile unsigned long long* st = g_state;
    if (tile == 0) {
        if (tid == 0) {
            st[0] = ((unsigned long long)total << 2) | 2ULL;
            s_excl = 0;
        }
    } else {
        if (tid == 0)
            st[tile] = ((unsigned long long)total << 2) | 1ULL;
        if (tid < 32) {
            int excl = 0;
            int t = tile - 1;
            while (true) {
                int idx = t - tid;
                unsigned long long s;
                if (idx >= 0) {
                    do { s = st[idx]; } while ((s & 3ULL) == 0ULL);
                } else {
                    s = 2ULL;
                }
                unsigned pm = __ballot_sync(0xffffffffu, (s & 3ULL) == 2ULL);
                int value = (int)(s >> 2);
                if (pm) {
                    int pl = __ffs(pm) - 1;
                    int contrib = (tid <= pl) ? value : 0;
                    excl += __reduce_add_sync(0xffffffffu, contrib);
                    break;
                } else {
                    excl += __reduce_add_sync(0xffffffffu, value);
                    t -= 32;
                }
            }
            if (tid == 0) {
                st[tile] = ((unsigned long long)(excl + total) << 2) | 2ULL;
                s_excl = excl;
            }
        }
    }
    __syncthreads();
    int base = s_excl;
    if (i < N_NODES) {
        int o = base + val - deg;
        g_off[i] = o;
        g_cur[i] = o;
        g_rsq[i] = rsqrtf((float)(deg > 0 ? deg : 1));
    }
    if (tile == 0 && tid == 0) g_off[N_NODES] = N_EDGES;
}

__global__ void k_fill_tohalf(const int* __restrict__ src,
                              const int* __restrict__ dst,
                              const float* __restrict__ x,
                              const float* __restrict__ W1a,
                              const float* __restrict__ W2a,
                              const float* __restrict__ W1b,
                              const float* __restrict__ W2b) {
    int i = blockIdx.x * blockDim.x + threadIdx.x;
    if (i < N_NODES * D / 4) {
        float4 v = ((const float4*)x)[i];
        half2 a = __floats2half2_rn(v.x, v.y);
        half2 b = __floats2half2_rn(v.z, v.w);
        uint2 o;
        o.x = *(unsigned int*)&a;
        o.y = *(unsigned int*)&b;
        ((uint2*)g_xh)[i] = o;
    }
    if (i < 4096) {
        g_w16[0][i]        = __float2half(W1a[i]);
        g_w16[0][4096 + i] = __float2half(W2a[i]);
        g_w16[1][i]        = __float2half(W1b[i]);
        g_w16[1][4096 + i] = __float2half(W2b[i]);
    }
    if (i < N_EDGES) {
        int d = dst[i];
        int s = src[i];
        float w = g_rsq[s] * g_rsq[d];
        int pos = atomicAdd(&g_cur[d], 1);
        g_edge[pos] = make_int2(s, __float_as_int(w));
    }
}

// ---------------- mma helpers ----------------
__device__ __forceinline__ unsigned smem_u32(const void* p) {
    return (unsigned)__cvta_generic_to_shared(p);
}
__device__ __forceinline__ void ldmatrix_x4(unsigned* a, unsigned addr) {
    asm volatile("ldmatrix.sync.aligned.m8n8.x4.shared.b16 {%0,%1,%2,%3}, [%4];"
                 : "=r"(a[0]), "=r"(a[1]), "=r"(a[2]), "=r"(a[3]) : "r"(addr));
}
__device__ __forceinline__ void ldmatrix_x2_trans(unsigned* b, unsigned addr) {
    asm volatile("ldmatrix.sync.aligned.m8n8.x2.trans.shared.b16 {%0,%1}, [%2];"
                 : "=r"(b[0]), "=r"(b[1]) : "r"(addr));
}
__device__ __forceinline__ void mma16816(float* d, const unsigned* a,
                                         const unsigned* b) {
    asm volatile(
        "mma.sync.aligned.m16n8k16.row.col.f32.f16.f16.f32 "
        "{%0,%1,%2,%3}, {%4,%5,%6,%7}, {%8,%9}, {%0,%1,%2,%3};"
        : "+f"(d[0]), "+f"(d[1]), "+f"(d[2]), "+f"(d[3])
        : "r"(a[0]), "r"(a[1]), "r"(a[2]), "r"(a[3]), "r"(b[0]), "r"(b[1]));
}

// ---------------- fused layer ----------------
__device__ __forceinline__ void cvt8(float* f, uint4 v) {
    float2 f0 = __half22float2(*(half2*)&v.x);
    float2 f1 = __half22float2(*(half2*)&v.y);
    float2 f2 = __half22float2(*(half2*)&v.z);
    float2 f3 = __half22float2(*(half2*)&v.w);
    f[0] = f0.x; f[1] = f0.y; f[2] = f1.x; f[3] = f1.y;
    f[4] = f2.x; f[5] = f2.y; f[6] = f3.x; f[7] = f3.y;
}

// block = 64 nodes. Gather: 8 threads/node, HFMA2 accumulation in fp16 with
// fp32 flush every 8 edges. Matvec: 16 warps HMMA (unchanged from R12).
__global__ void __launch_bounds__(TPB, 3) k_fused(
    const __half* __restrict__ hh,
    const __half* __restrict__ Wh,    // [128][64] fp16: k<64 = W1, k>=64 = W2
    float* __restrict__ out,          // [N,192] at colOff
    __half* __restrict__ houtH,       // may be null
    int do_relu, int colOff)
{
    extern __shared__ __align__(16) __half smem_h[];
    __half* sab = smem_h;                           // [NPB][AB_STRIDE_H]
    __half* sW  = smem_h + NPB * AB_STRIDE_H;       // [128][W_STRIDE_H]

    int tid = threadIdx.x;

    // ---- stage fp16 weights (pure copy) ----
    for (int i = tid; i < 1024; i += TPB) {
        int k = i >> 3, j = i & 7;
        *(uint4*)(sW + k * W_STRIDE_H + j * 8) =
            *(const uint4*)(Wh + k * 64 + j * 8);
    }

    // ---- gather: 8 threads/node, fp16 chunks flushed to fp32 ----
    int nl = tid >> 3;                 // 0..63
    int c  = tid & 7;                  // chunk 0..7
    int node = blockIdx.x * NPB + nl;
    if (node < N_NODES) {
        float accf[8];
#pragma unroll
        for (int j = 0; j < 8; j++) accf[j] = 0.f;
        int e = g_off[node];
        int end = g_off[node + 1];
        const uint4* h4 = (const uint4*)hh;

        while (e < end) {
            int stop = (end - e > 8) ? e + 8 : end;
            half2 a0 = __float2half2_rn(0.f), a1 = a0, a2 = a0, a3 = a0;
            int2 E = g_edge[e];
            for (;;) {
                int enx = e + 1;
                int2 P;
                if (enx < stop) P = g_edge[enx];
                uint4 v = h4[(size_t)E.x * 8 + c];
                half2 w = __float2half2_rn(__int_as_float(E.y));
                a0 = __hfma2(w, *(half2*)&v.x, a0);
                a1 = __hfma2(w, *(half2*)&v.y, a1);
                a2 = __hfma2(w, *(half2*)&v.z, a2);
                a3 = __hfma2(w, *(half2*)&v.w, a3);
                e = enx;
                if (e >= stop) break;
                E = P;
            }
            float2 f;
            f = __half22float2(a0); accf[0] += f.x; accf[1] += f.y;
            f = __half22float2(a1); accf[2] += f.x; accf[3] += f.y;
            f = __half22float2(a2); accf[4] += f.x; accf[5] += f.y;
            f = __half22float2(a3); accf[6] += f.x; accf[7] += f.y;
        }

        // a = x+s -> k cols 8c..8c+7 ; b = x*s -> k cols 64+8c..
        uint4 xv = ((const uint4*)(hh + (size_t)node * D))[c];
        float xf[8];
        cvt8(xf, xv);
        __half* row = sab + nl * AB_STRIDE_H;
        half2 pa[4], pb[4];
#pragma unroll
        for (int j = 0; j < 4; j++) {
            pa[j] = __floats2half2_rn(xf[2*j] + accf[2*j], xf[2*j+1] + accf[2*j+1]);
            pb[j] = __floats2half2_rn(xf[2*j] * accf[2*j], xf[2*j+1] * accf[2*j+1]);
        }
        *(uint4*)(row + 8 * c)      = *(uint4*)pa;
        *(uint4*)(row + 64 + 8 * c) = *(uint4*)pb;
    }
    __syncthreads();

    // ---- HMMA matvec ----
    int w = tid >> 5;
    int lane = tid & 31;
    int rtile = w >> 2;                // 0..3
    int cbase = (w & 3) * 2;           // ctiles cbase, cbase+1

    float d[2][4];
#pragma unroll
    for (int i = 0; i < 2; i++)
#pragma unroll
        for (int j = 0; j < 4; j++) d[i][j] = 0.f;

    unsigned a_addr = smem_u32(sab + (16 * rtile + (lane & 15)) * AB_STRIDE_H
                               + ((lane >> 4) << 3));
#pragma unroll
    for (int ks = 0; ks < 8; ks++) {
        unsigned afr[4];
        ldmatrix_x4(afr, a_addr + ks * 32);   // +16 halves = 32B per kstep
#pragma unroll
        for (int ci = 0; ci < 2; ci++) {
            int cb = (cbase + ci) << 3;
            unsigned b_addr = smem_u32(sW + (ks * 16 + (lane & 15)) * W_STRIDE_H + cb);
            unsigned bfr[2];
            ldmatrix_x2_trans(bfr, b_addr);
            mma16816(d[ci], afr, bfr);
        }
    }

    // ---- epilogue ----
    int r0 = lane >> 2;
    int cc = (lane & 3) << 1;
    int node0 = blockIdx.x * NPB + 16 * rtile + r0;
    int node1 = node0 + 8;
#pragma unroll
    for (int ci = 0; ci < 2; ci++) {
        int col = ((cbase + ci) << 3) + cc;
        float v0 = d[ci][0], v1 = d[ci][1], v2 = d[ci][2], v3 = d[ci][3];
        if (do_relu) {
            v0 = v0 > 0.f ? v0 : NEG_SLOPE * v0;
            v1 = v1 > 0.f ? v1 : NEG_SLOPE * v1;
            v2 = v2 > 0.f ? v2 : NEG_SLOPE * v2;
            v3 = v3 > 0.f ? v3 : NEG_SLOPE * v3;
        }
        if (node0 < N_NODES) {
            *(float2*)(out + (size_t)node0 * 192 + colOff + col) =
                make_float2(v0, v1);
            if (houtH) {
                half2 h = __floats2half2_rn(v0, v1);
                *(unsigned*)(houtH + (size_t)node0 * D + col) = *(unsigned*)&h;
            }
        }
        if (node1 < N_NODES) {
            *(float2*)(out + (size_t)node1 * 192 + colOff + col) =
                make_float2(v2, v3);
            if (houtH) {
                half2 h = __floats2half2_rn(v2, v3);
                *(unsigned*)(houtH + (size_t)node1 * D + col) = *(unsigned*)&h;
            }
        }
    }
}

// ---------------- launch ----------------
extern "C" void kernel_launch(void* const* d_in, const int* in_sizes, int n_in,
                              void* d_out, int out_size) {
    const float* x   = (const float*)d_in[0];
    const float* W1a = (const float*)d_in[1];
    const float* W2a = (const float*)d_in[2];
    const float* W1b = (const float*)d_in[3];
    const float* W2b = (const float*)d_in[4];
    const int*   src = (const int*)d_in[5];
    const int*   dst = (const int*)d_in[6];
    float* out = (float*)d_out;

    __half* xh;  cudaGetSymbolAddress((void**)&xh,  g_xh);
    __half* hAh; cudaGetSymbolAddress((void**)&hAh, g_hAh);
    __half* hBh; cudaGetSymbolAddress((void**)&hBh, g_hBh);
    __half* wh;  cudaGetSymbolAddress((void**)&wh,  g_w16);
    void* degP;  cudaGetSymbolAddress(&degP, g_deg);
    void* tkP;   cudaGetSymbolAddress(&tkP, g_ticket);
    void* stP;   cudaGetSymbolAddress(&stP, g_state);

    cudaFuncSetAttribute(k_fused, cudaFuncAttributeMaxDynamicSharedMemorySize,
                         SMEM_BYTES);

    const int TB = 256;
    int gE = (N_EDGES + TB - 1) / TB;
    int gF = (N_NODES + NPB - 1) / NPB;   // 1563

    cudaMemsetAsync(degP, 0, N_NODES * sizeof(int));
    cudaMemsetAsync(tkP, 0, sizeof(int));
    cudaMemsetAsync(stP, 0, NTILES * sizeof(unsigned long long));

    k_count<<<gE, TB>>>(dst);
    k_scan<<<NTILES, 256>>>();
    k_fill_tohalf<<<gE, TB>>>(src, dst, x, W1a, W2a, W1b, W2b);

    k_fused<<<gF, TPB, SMEM_BYTES>>>(xh, wh,         out, hAh, 1, 0);
    k_fused<<<gF, TPB, SMEM_BYTES>>>(hAh, wh + 8192, out, hBh, 1, 64);
    k_fused<<<gF, TPB, SMEM_BYTES>>>(hBh, wh + 8192, out, (__half*)0, 0, 128);
}

// round 15
// speedup vs baseline: 1.0676x; 1.0676x over previous
#include <cuda_runtime.h>
#include <cuda_fp16.h>
#include <math.h>

#define N_NODES 100000
#define N_EDGES 3200000
#define D 64
#define NEG_SLOPE 0.01f
#define NTILES ((N_NODES + 255) / 256)   // 391

#define NPB 64           // nodes per fused block
#define TPB 512          // 8 threads/node (gather); 16 warps (mma)
#define AB_STRIDE_H 136  // halves per ab row (272B: conflict-free rotation)
#define W_STRIDE_H 72    // halves per weight row (144B: same rotation)
#define SMEM_AB_BYTES (NPB * AB_STRIDE_H * 2)        // 17408
#define SMEM_W_BYTES  (128 * W_STRIDE_H * 2)         // 18432
#define SMEM_PERM_BYTES (NPB * 4)                    // 256
#define SMEM_BYTES    (SMEM_AB_BYTES + SMEM_W_BYTES + SMEM_PERM_BYTES)

// ---------------- device scratch (no allocations allowed) ----------------
__device__ __half g_xh [N_NODES * D];   // fp16 x
__device__ __half g_hAh[N_NODES * D];   // fp16 h1
__device__ __half g_hBh[N_NODES * D];   // fp16 h2
__device__ __half g_w16[2][8192];       // fp16 weights: [layerSel][k*64+n]
__device__ float  g_rsq[N_NODES];
__device__ int    g_deg[N_NODES];
__device__ int    g_off[N_NODES + 1];
__device__ int    g_cur[N_NODES];
__device__ int    g_perm[N_NODES];      // nodes grouped by degree (desc)
__device__ int    g_hist[256];
__device__ int    g_bincur[256];
__device__ int2   g_edge[N_EDGES];      // {src, bitcast(w)} grouped by dst
__device__ int                g_ticket;
__device__ unsigned long long g_state[NTILES];

// ---------------- precompute kernels ----------------
__global__ void k_count(const int* __restrict__ dst) {
    int e = blockIdx.x * blockDim.x + threadIdx.x;
    if (e < N_EDGES) atomicAdd(&g_deg[dst[e]], 1);
}

__global__ void __launch_bounds__(256) k_scan() {
    __shared__ int sh[256];
    __shared__ int s_tile, s_excl;
    int tid = threadIdx.x;
    if (tid == 0) s_tile = atomicAdd(&g_ticket, 1);
    __syncthreads();
    int tile = s_tile;
    int i = tile * 256 + tid;
    int deg = (i < N_NODES) ? g_deg[i] : 0;
    int val = deg;
    sh[tid] = val;
    __syncthreads();
    for (int ofs = 1; ofs < 256; ofs <<= 1) {
        int t = (tid >= ofs) ? sh[tid - ofs] : 0;
        __syncthreads();
        val += t;
        sh[tid] = val;
        __syncthreads();
    }
    int total = sh[255];

    volatile unsigned long long* st = g_state;
    if (tile == 0) {
        if (tid == 0) {
            st[0] = ((unsigned long long)total << 2) | 2ULL;
            s_excl = 0;
        }
    } else {
        if (tid == 0)
            st[tile] = ((unsigned long long)total << 2) | 1ULL;
        if (tid < 32) {
            int excl = 0;
            int t = tile - 1;
            while (true) {
                int idx = t - tid;
                unsigned long long s;
                if (idx >= 0) {
                    do { s = st[idx]; } while ((s & 3ULL) == 0ULL);
                } else {
                    s = 2ULL;
                }
                unsigned pm = __ballot_sync(0xffffffffu, (s & 3ULL) == 2ULL);
                int value = (int)(s >> 2);
                if (pm) {
                    int pl = __ffs(pm) - 1;
                    int contrib = (tid <= pl) ? value : 0;
                    excl += __reduce_add_sync(0xffffffffu, contrib);
                    break;
                } else {
                    excl += __reduce_add_sync(0xffffffffu, value);
                    t -= 32;
                }
            }
            if (tid == 0) {
                st[tile] = ((unsigned long long)(excl + total) << 2) | 2ULL;
                s_excl = excl;
            }
        }
    }
    __syncthreads();
    int base = s_excl;
    if (i < N_NODES) {
        int o = base + val - deg;
        g_off[i] = o;
        g_cur[i] = o;
        g_rsq[i] = rsqrtf((float)(deg > 0 ? deg : 1));
    }
    if (tile == 0 && tid == 0) g_off[N_NODES] = N_EDGES;
}

// degree histogram (shared pre-aggregation)
__global__ void __launch_bounds__(256) k_hist() {
    __shared__ int sh[256];
    int tid = threadIdx.x;
    sh[tid] = 0;
    __syncthreads();
    int i = blockIdx.x * 256 + tid;
    if (i < N_NODES) {
        int b = g_deg[i];
        b = b > 255 ? 255 : b;
        atomicAdd(&sh[b], 1);
    }
    __syncthreads();
    if (sh[tid]) atomicAdd(&g_hist[tid], sh[tid]);
}

// bin offsets, DESCENDING degree (heavy blocks scheduled first)
__global__ void __launch_bounds__(256) k_binscan() {
    __shared__ int sh[256];
    int tid = threadIdx.x;
    int h = g_hist[tid];
    int val = h;
    sh[tid] = val;
    __syncthreads();
    for (int ofs = 1; ofs < 256; ofs <<= 1) {
        int t = (tid >= ofs) ? sh[tid - ofs] : 0;
        __syncthreads();
        val += t;
        sh[tid] = val;
        __syncthreads();
    }
    // start of bin tid (descending) = count of all nodes with degree > tid
    g_bincur[tid] = N_NODES - val + (val - (val - h)) - h + (N_NODES - val);
    // simplify: nodes with deg > tid = N_NODES - inclusive_scan(tid)
    g_bincur[tid] = N_NODES - val;
}

__global__ void k_permute() {
    int i = blockIdx.x * blockDim.x + threadIdx.x;
    if (i < N_NODES) {
        int b = g_deg[i];
        b = b > 255 ? 255 : b;
        int pos = atomicAdd(&g_bincur[b], 1);
        g_perm[pos] = i;
    }
}

__global__ void k_fill_tohalf(const int* __restrict__ src,
                              const int* __restrict__ dst,
                              const float* __restrict__ x,
                              const float* __restrict__ W1a,
                              const float* __restrict__ W2a,
                              const float* __restrict__ W1b,
                              const float* __restrict__ W2b) {
    int i = blockIdx.x * blockDim.x + threadIdx.x;
    if (i < N_NODES * D / 4) {
        float4 v = ((const float4*)x)[i];
        half2 a = __floats2half2_rn(v.x, v.y);
        half2 b = __floats2half2_rn(v.z, v.w);
        uint2 o;
        o.x = *(unsigned int*)&a;
        o.y = *(unsigned int*)&b;
        ((uint2*)g_xh)[i] = o;
    }
    if (i < 4096) {
        g_w16[0][i]        = __float2half(W1a[i]);
        g_w16[0][4096 + i] = __float2half(W2a[i]);
        g_w16[1][i]        = __float2half(W1b[i]);
        g_w16[1][4096 + i] = __float2half(W2b[i]);
    }
    if (i < N_EDGES) {
        int d = dst[i];
        int s = src[i];
        float w = g_rsq[s] * g_rsq[d];
        int pos = atomicAdd(&g_cur[d], 1);
        g_edge[pos] = make_int2(s, __float_as_int(w));
    }
}

// ---------------- mma helpers ----------------
__device__ __forceinline__ unsigned smem_u32(const void* p) {
    return (unsigned)__cvta_generic_to_shared(p);
}
__device__ __forceinline__ void ldmatrix_x4(unsigned* a, unsigned addr) {
    asm volatile("ldmatrix.sync.aligned.m8n8.x4.shared.b16 {%0,%1,%2,%3}, [%4];"
                 : "=r"(a[0]), "=r"(a[1]), "=r"(a[2]), "=r"(a[3]) : "r"(addr));
}
__device__ __forceinline__ void ldmatrix_x2_trans(unsigned* b, unsigned addr) {
    asm volatile("ldmatrix.sync.aligned.m8n8.x2.trans.shared.b16 {%0,%1}, [%2];"
                 : "=r"(b[0]), "=r"(b[1]) : "r"(addr));
}
__device__ __forceinline__ void mma16816(float* d, const unsigned* a,
                                         const unsigned* b) {
    asm volatile(
        "mma.sync.aligned.m16n8k16.row.col.f32.f16.f16.f32 "
        "{%0,%1,%2,%3}, {%4,%5,%6,%7}, {%8,%9}, {%0,%1,%2,%3};"
        : "+f"(d[0]), "+f"(d[1]), "+f"(d[2]), "+f"(d[3])
        : "r"(a[0]), "r"(a[1]), "r"(a[2]), "r"(a[3]), "r"(b[0]), "r"(b[1]));
}

// ---------------- fused layer ----------------
__device__ __forceinline__ void cvt8(float* f, uint4 v) {
    float2 f0 = __half22float2(*(half2*)&v.x);
    float2 f1 = __half22float2(*(half2*)&v.y);
    float2 f2 = __half22float2(*(half2*)&v.z);
    float2 f3 = __half22float2(*(half2*)&v.w);
    f[0] = f0.x; f[1] = f0.y; f[2] = f1.x; f[3] = f1.y;
    f[4] = f2.x; f[5] = f2.y; f[6] = f3.x; f[7] = f3.y;
}

__global__ void __launch_bounds__(TPB, 3) k_fused(
    const __half* __restrict__ hh,
    const __half* __restrict__ Wh,    // [128][64] fp16: k<64 = W1, k>=64 = W2
    float* __restrict__ out,          // [N,192] at colOff
    __half* __restrict__ houtH,       // may be null
    int do_relu, int colOff)
{
    extern __shared__ __align__(16) __half smem_h[];
    __half* sab = smem_h;                           // [NPB][AB_STRIDE_H]
    __half* sW  = smem_h + NPB * AB_STRIDE_H;       // [128][W_STRIDE_H]
    int* sperm  = (int*)(smem_h + NPB * AB_STRIDE_H + 128 * W_STRIDE_H);

    int tid = threadIdx.x;

    // ---- stage fp16 weights + this block's 64 perm entries ----
    for (int i = tid; i < 1024; i += TPB) {
        int k = i >> 3, j = i & 7;
        *(uint4*)(sW + k * W_STRIDE_H + j * 8) =
            *(const uint4*)(Wh + k * 64 + j * 8);
    }
    if (tid < NPB) {
        int idx = blockIdx.x * NPB + tid;
        sperm[tid] = (idx < N_NODES) ? g_perm[idx] : -1;
    }
    __syncthreads();

    // ---- gather: 8 threads/node, batch-4 edges, HFMA2 + fp32 flush ----
    int nl = tid >> 3;                 // 0..63
    int c  = tid & 7;                  // chunk 0..7
    int node = sperm[nl];
    if (node >= 0) {
        float accf[8];
#pragma unroll
        for (int j = 0; j < 8; j++) accf[j] = 0.f;
        int e = g_off[node];
        int end = g_off[node + 1];
        const uint4* h4 = (const uint4*)hh;

        while (e < end) {
            int r = end - e;
            int2 E0 = g_edge[e];
            int2 E1 = (r > 1) ? g_edge[e + 1] : E0;
            int2 E2 = (r > 2) ? g_edge[e + 2] : E0;
            int2 E3 = (r > 3) ? g_edge[e + 3] : E0;
            float w0f = __int_as_float(E0.y);
            float w1f = (r > 1) ? __int_as_float(E1.y) : 0.f;
            float w2f = (r > 2) ? __int_as_float(E2.y) : 0.f;
            float w3f = (r > 3) ? __int_as_float(E3.y) : 0.f;
            uint4 v0 = h4[(size_t)E0.x * 8 + c];
            uint4 v1 = h4[(size_t)E1.x * 8 + c];
            uint4 v2 = h4[(size_t)E2.x * 8 + c];
            uint4 v3 = h4[(size_t)E3.x * 8 + c];
            half2 w0 = __float2half2_rn(w0f);
            half2 w1 = __float2half2_rn(w1f);
            half2 w2 = __float2half2_rn(w2f);
            half2 w3 = __float2half2_rn(w3f);
            half2 a0, a1, a2, a3;
            a0 = __hmul2(w0, *(half2*)&v0.x);
            a1 = __hmul2(w0, *(half2*)&v0.y);
            a2 = __hmul2(w0, *(half2*)&v0.z);
            a3 = __hmul2(w0, *(half2*)&v0.w);
            a0 = __hfma2(w1, *(half2*)&v1.x, a0);
            a1 = __hfma2(w1, *(half2*)&v1.y, a1);
            a2 = __hfma2(w1, *(half2*)&v1.z, a2);
            a3 = __hfma2(w1, *(half2*)&v1.w, a3);
            a0 = __hfma2(w2, *(half2*)&v2.x, a0);
            a1 = __hfma2(w2, *(half2*)&v2.y, a1);
            a2 = __hfma2(w2, *(half2*)&v2.z, a2);
            a3 = __hfma2(w2, *(half2*)&v2.w, a3);
            a0 = __hfma2(w3, *(half2*)&v3.x, a0);
            a1 = __hfma2(w3, *(half2*)&v3.y, a1);
            a2 = __hfma2(w3, *(half2*)&v3.z, a2);
            a3 = __hfma2(w3, *(half2*)&v3.w, a3);
            float2 f;
            f = __half22float2(a0); accf[0] += f.x; accf[1] += f.y;
            f = __half22float2(a1); accf[2] += f.x; accf[3] += f.y;
            f = __half22float2(a2); accf[4] += f.x; accf[5] += f.y;
            f = __half22float2(a3); accf[6] += f.x; accf[7] += f.y;
            e += 4;
        }

        // a = x+s -> k cols 8c..8c+7 ; b = x*s -> k cols 64+8c..
        uint4 xv = ((const uint4*)(hh + (size_t)node * D))[c];
        float xf[8];
        cvt8(xf, xv);
        __half* row = sab + nl * AB_STRIDE_H;
        half2 pa[4], pb[4];
#pragma unroll
        for (int j = 0; j < 4; j++) {
            pa[j] = __floats2half2_rn(xf[2*j] + accf[2*j], xf[2*j+1] + accf[2*j+1]);
            pb[j] = __floats2half2_rn(xf[2*j] * accf[2*j], xf[2*j+1] * accf[2*j+1]);
        }
        *(uint4*)(row + 8 * c)      = *(uint4*)pa;
        *(uint4*)(row + 64 + 8 * c) = *(uint4*)pb;
    }
    __syncthreads();

    // ---- HMMA matvec ----
    int w = tid >> 5;
    int lane = tid & 31;
    int rtile = w >> 2;                // 0..3
    int cbase = (w & 3) * 2;           // ctiles cbase, cbase+1

    float d[2][4];
#pragma unroll
    for (int i = 0; i < 2; i++)
#pragma unroll
        for (int j = 0; j < 4; j++) d[i][j] = 0.f;

    unsigned a_addr = smem_u32(sab + (16 * rtile + (lane & 15)) * AB_STRIDE_H
                               + ((lane >> 4) << 3));
#pragma unroll
    for (int ks = 0; ks < 8; ks++) {
        unsigned afr[4];
        ldmatrix_x4(afr, a_addr + ks * 32);   // +16 halves = 32B per kstep
#pragma unroll
        for (int ci = 0; ci < 2; ci++) {
            int cb = (cbase + ci) << 3;
            unsigned b_addr = smem_u32(sW + (ks * 16 + (lane & 15)) * W_STRIDE_H + cb);
            unsigned bfr[2];
            ldmatrix_x2_trans(bfr, b_addr);
            mma16816(d[ci], afr, bfr);
        }
    }

    // ---- epilogue ----
    int r0 = lane >> 2;
    int cc = (lane & 3) << 1;
    int node0 = sperm[16 * rtile + r0];
    int node1 = sperm[16 * rtile + r0 + 8];
#pragma unroll
    for (int ci = 0; ci < 2; ci++) {
        int col = ((cbase + ci) << 3) + cc;
        float v0 = d[ci][0], v1 = d[ci][1], v2 = d[ci][2], v3 = d[ci][3];
        if (do_relu) {
            v0 = v0 > 0.f ? v0 : NEG_SLOPE * v0;
            v1 = v1 > 0.f ? v1 : NEG_SLOPE * v1;
            v2 = v2 > 0.f ? v2 : NEG_SLOPE * v2;
            v3 = v3 > 0.f ? v3 : NEG_SLOPE * v3;
        }
        if (node0 >= 0) {
            *(float2*)(out + (size_t)node0 * 192 + colOff + col) =
                make_float2(v0, v1);
            if (houtH) {
                half2 h = __floats2half2_rn(v0, v1);
                *(unsigned*)(houtH + (size_t)node0 * D + col) = *(unsigned*)&h;
            }
        }
        if (node1 >= 0) {
            *(float2*)(out + (size_t)node1 * 192 + colOff + col) =
                make_float2(v2, v3);
            if (houtH) {
                half2 h = __floats2half2_rn(v2, v3);
                *(unsigned*)(houtH + (size_t)node1 * D + col) = *(unsigned*)&h;
            }
        }
    }
}

// ---------------- launch ----------------
extern "C" void kernel_launch(void* const* d_in, const int* in_sizes, int n_in,
                              void* d_out, int out_size) {
    const float* x   = (const float*)d_in[0];
    const float* W1a = (const float*)d_in[1];
    const float* W2a = (const float*)d_in[2];
    const float* W1b = (const float*)d_in[3];
    const float* W2b = (const float*)d_in[4];
    const int*   src = (const int*)d_in[5];
    const int*   dst = (const int*)d_in[6];
    float* out = (float*)d_out;

    __half* xh;  cudaGetSymbolAddress((void**)&xh,  g_xh);
    __half* hAh; cudaGetSymbolAddress((void**)&hAh, g_hAh);
    __half* hBh; cudaGetSymbolAddress((void**)&hBh, g_hBh);
    __half* wh;  cudaGetSymbolAddress((void**)&wh,  g_w16);
    void* degP;  cudaGetSymbolAddress(&degP, g_deg);
    void* tkP;   cudaGetSymbolAddress(&tkP, g_ticket);
    void* stP;   cudaGetSymbolAddress(&stP, g_state);
    void* hiP;   cudaGetSymbolAddress(&hiP, g_hist);

    cudaFuncSetAttribute(k_fused, cudaFuncAttributeMaxDynamicSharedMemorySize,
                         SMEM_BYTES);

    const int TB = 256;
    int gE = (N_EDGES + TB - 1) / TB;
    int gN = (N_NODES + TB - 1) / TB;
    int gF = (N_NODES + NPB - 1) / NPB;   // 1563

    cudaMemsetAsync(degP, 0, N_NODES * sizeof(int));
    cudaMemsetAsync(tkP, 0, sizeof(int));
    cudaMemsetAsync(stP, 0, NTILES * sizeof(unsigned long long));
    cudaMemsetAsync(hiP, 0, 256 * sizeof(int));

    k_count<<<gE, TB>>>(dst);
    k_scan<<<NTILES, 256>>>();
    k_hist<<<gN, 256>>>();
    k_binscan<<<1, 256>>>();
    k_permute<<<gN, TB>>>();
    k_fill_tohalf<<<gE, TB>>>(src, dst, x, W1a, W2a, W1b, W2b);

    k_fused<<<gF, TPB, SMEM_BYTES>>>(xh, wh,         out, hAh, 1, 0);
    k_fused<<<gF, TPB, SMEM_BYTES>>>(hAh, wh + 8192, out, hBh, 1, 64);
    k_fused<<<gF, TPB, SMEM_BYTES>>>(hBh, wh + 8192, out, (__half*)0, 0, 128);
}

// round 17
// speedup vs baseline: 1.2361x; 1.1578x over previous
#include <cuda_runtime.h>
#include <cuda_fp16.h>
#include <math.h>

#define N_NODES 100000
#define N_EDGES 3200000
#define D 64
#define NEG_SLOPE 0.01f
#define NTILES ((N_NODES + 255) / 256)   // 391

#define NPB 64           // nodes per fused block
#define TPB 512          // 8 threads/node (gather); 16 warps (mma)
#define AB_STRIDE_H 136  // halves per ab row (272B: conflict-free rotation)
#define W_STRIDE_H 72    // halves per weight row (144B: same rotation)
#define SMEM_AB_BYTES (NPB * AB_STRIDE_H * 2)        // 17408
#define SMEM_W_BYTES  (128 * W_STRIDE_H * 2)         // 18432
#define SMEM_PERM_BYTES (NPB * 4)                    // 256
#define SMEM_BYTES    (SMEM_AB_BYTES + SMEM_W_BYTES + SMEM_PERM_BYTES)

#define EDGE_CAP (N_EDGES + 8 * N_NODES)

// ---------------- device scratch (no allocations allowed) ----------------
// feature tables hold SCALED rows y = rsq * h; row N_NODES is all-zero (pad)
__device__ __half g_xh [(N_NODES + 1) * D];
__device__ __half g_hAh[(N_NODES + 1) * D];
__device__ __half g_hBh[(N_NODES + 1) * D];
__device__ __half g_w16[2][8192];       // fp16 weights: [layerSel][k*64+n]
__device__ float  g_rsq[N_NODES];       // 1/sqrt(max(deg,1))
__device__ float  g_sqd[N_NODES];       // sqrt(max(deg,1))
__device__ int    g_deg[N_NODES];
__device__ int    g_off[N_NODES + 1];   // PADDED csr offsets (multiples of 8)
__device__ int    g_cur[N_NODES];
__device__ int    g_perm[N_NODES];      // nodes grouped by degree (desc)
__device__ int    g_hist[256];
__device__ int    g_bincur[256];
__device__ int    g_edge[EDGE_CAP];     // src ids, padded with N_NODES
__device__ int                g_ticket;
__device__ unsigned long long g_state[NTILES];

// ---------------- precompute kernels ----------------
__global__ void k_count(const int* __restrict__ dst) {
    int e = blockIdx.x * blockDim.x + threadIdx.x;
    if (e < N_EDGES) atomicAdd(&g_deg[dst[e]], 1);
}

// single-pass scan over PADDED degree + rsq/sqd + degree histogram
__global__ void __launch_bounds__(256) k_scan() {
    __shared__ int sh[256];
    __shared__ int shh[256];
    __shared__ int s_tile, s_excl;
    int tid = threadIdx.x;
    shh[tid] = 0;
    if (tid == 0) s_tile = atomicAdd(&g_ticket, 1);
    __syncthreads();
    int tile = s_tile;
    int i = tile * 256 + tid;
    int deg = (i < N_NODES) ? g_deg[i] : 0;
    int pd = (i < N_NODES) ? ((deg + 7) & ~7) : 0;   // padded degree
    if (i < N_NODES) atomicAdd(&shh[deg > 255 ? 255 : deg], 1);
    int val = pd;
    sh[tid] = val;
    __syncthreads();
    for (int ofs = 1; ofs < 256; ofs <<= 1) {
        int t = (tid >= ofs) ? sh[tid - ofs] : 0;
        __syncthreads();
        val += t;
        sh[tid] = val;
        __syncthreads();
    }
    int total = sh[255];

    volatile unsigned long long* st = g_state;
    if (tile == 0) {
        if (tid == 0) {
            st[0] = ((unsigned long long)total << 2) | 2ULL;
            s_excl = 0;
        }
    } else {
        if (tid == 0)
            st[tile] = ((unsigned long long)total << 2) | 1ULL;
        if (tid < 32) {
            int excl = 0;
            int t = tile - 1;
            while (true) {
                int idx = t - tid;
                unsigned long long s;
                if (idx >= 0) {
                    do { s = st[idx]; } while ((s & 3ULL) == 0ULL);
                } else {
                    s = 2ULL;
                }
                unsigned pm = __ballot_sync(0xffffffffu, (s & 3ULL) == 2ULL);
                int value = (int)(s >> 2);
                if (pm) {
                    int pl = __ffs(pm) - 1;
                    int contrib = (tid <= pl) ? value : 0;
                    excl += __reduce_add_sync(0xffffffffu, contrib);
                    break;
                } else {
                    excl += __reduce_add_sync(0xffffffffu, value);
                    t -= 32;
                }
            }
            if (tid == 0) {
                st[tile] = ((unsigned long long)(excl + total) << 2) | 2ULL;
                s_excl = excl;
            }
        }
    }
    __syncthreads();
    int base = s_excl;
    if (i < N_NODES) {
        int o = base + val - pd;
        g_off[i] = o;
        g_cur[i] = o;
        float dm = (float)(deg > 0 ? deg : 1);
        g_rsq[i] = rsqrtf(dm);
        g_sqd[i] = sqrtf(dm);
        if (i == N_NODES - 1) g_off[N_NODES] = o + pd;
    }
    if (shh[tid]) atomicAdd(&g_hist[tid], shh[tid]);
}

// bin offsets, DESCENDING degree (heavy blocks scheduled first)
__global__ void __launch_bounds__(256) k_binscan() {
    __shared__ int sh[256];
    int tid = threadIdx.x;
    int h = g_hist[tid];
    int val = h;
    sh[tid] = val;
    __syncthreads();
    for (int ofs = 1; ofs < 256; ofs <<= 1) {
        int t = (tid >= ofs) ? sh[tid - ofs] : 0;
        __syncthreads();
        val += t;
        sh[tid] = val;
        __syncthreads();
    }
    g_bincur[tid] = N_NODES - val;   // nodes with deg-bin > tid
}

// fill CSR (src only) + pads + permute + scaled-fp16 x + fp16 weights
__global__ void k_fill_all(const int* __restrict__ src,
                           const int* __restrict__ dst,
                           const float* __restrict__ x,
                           const float* __restrict__ W1a,
                           const float* __restrict__ W2a,
                           const float* __restrict__ W1b,
                           const float* __restrict__ W2b) {
    int i = blockIdx.x * blockDim.x + threadIdx.x;
    if (i < N_NODES * D / 4) {
        int node = i >> 4;
        float r = g_rsq[node];
        float4 v = ((const float4*)x)[i];
        half2 a = __floats2half2_rn(r * v.x, r * v.y);
        half2 b = __floats2half2_rn(r * v.z, r * v.w);
        uint2 o;
        o.x = *(unsigned int*)&a;
        o.y = *(unsigned int*)&b;
        ((uint2*)g_xh)[i] = o;
    }
    if (i < 4096) {
        g_w16[0][i]        = __float2half(W1a[i]);
        g_w16[0][4096 + i] = __float2half(W2a[i]);
        g_w16[1][i]        = __float2half(W1b[i]);
        g_w16[1][4096 + i] = __float2half(W2b[i]);
    }
    if (i < N_EDGES) {
        int d = dst[i];
        int pos = atomicAdd(&g_cur[d], 1);
        g_edge[pos] = src[i];
    }
    if (i < N_NODES) {
        // pads (disjoint from real slots) + degree-sorted permutation
        int o = g_off[i];
        int deg = g_deg[i];
        int pd = (deg + 7) & ~7;
        for (int p = deg; p < pd; p++) g_edge[o + p] = N_NODES;
        int b = deg > 255 ? 255 : deg;
        int pos = atomicAdd(&g_bincur[b], 1);
        g_perm[pos] = i;
    }
}

// ---------------- mma helpers ----------------
__device__ __forceinline__ unsigned smem_u32(const void* p) {
    return (unsigned)__cvta_generic_to_shared(p);
}
__device__ __forceinline__ void ldmatrix_x4(unsigned* a, unsigned addr) {
    asm volatile("ldmatrix.sync.aligned.m8n8.x4.shared.b16 {%0,%1,%2,%3}, [%4];"
                 : "=r"(a[0]), "=r"(a[1]), "=r"(a[2]), "=r"(a[3]) : "r"(addr));
}
__device__ __forceinline__ void ldmatrix_x2_trans(unsigned* b, unsigned addr) {
    asm volatile("ldmatrix.sync.aligned.m8n8.x2.trans.shared.b16 {%0,%1}, [%2];"
                 : "=r"(b[0]), "=r"(b[1]) : "r"(addr));
}
__device__ __forceinline__ void mma16816(float* d, const unsigned* a,
                                         const unsigned* b) {
    asm volatile(
        "mma.sync.aligned.m16n8k16.row.col.f32.f16.f16.f32 "
        "{%0,%1,%2,%3}, {%4,%5,%6,%7}, {%8,%9}, {%0,%1,%2,%3};"
        : "+f"(d[0]), "+f"(d[1]), "+f"(d[2]), "+f"(d[3])
        : "r"(a[0]), "r"(a[1]), "r"(a[2]), "r"(a[3]), "r"(b[0]), "r"(b[1]));
}

// ---------------- fused layer ----------------
__device__ __forceinline__ void cvt8(float* f, uint4 v) {
    float2 f0 = __half22float2(*(half2*)&v.x);
    float2 f1 = __half22float2(*(half2*)&v.y);
    float2 f2 = __half22float2(*(half2*)&v.z);
    float2 f3 = __half22float2(*(half2*)&v.w);
    f[0] = f0.x; f[1] = f0.y; f[2] = f1.x; f[3] = f1.y;
    f[4] = f2.x; f[5] = f2.y; f[6] = f3.x; f[7] = f3.y;
}
#define HACC(A, V) \
    A##0 = __hadd2(A##0, *(half2*)&V.x); \
    A##1 = __hadd2(A##1, *(half2*)&V.y); \
    A##2 = __hadd2(A##2, *(half2*)&V.z); \
    A##3 = __hadd2(A##3, *(half2*)&V.w)

__global__ void __launch_bounds__(TPB, 3) k_fused(
    const __half* __restrict__ hh,    // SCALED fp16 rows y = rsq*h; row N_NODES = 0
    const __half* __restrict__ Wh,    // [128][64] fp16: k<64 = W1, k>=64 = W2
    float* __restrict__ out,          // [N,192] at colOff
    __half* __restrict__ houtH,       // next scaled table, may be null
    int do_relu, int colOff)
{
    extern __shared__ __align__(16) __half smem_h[];
    __half* sab = smem_h;                           // [NPB][AB_STRIDE_H]
    __half* sW  = smem_h + NPB * AB_STRIDE_H;       // [128][W_STRIDE_H]
    int* sperm  = (int*)(smem_h + NPB * AB_STRIDE_H + 128 * W_STRIDE_H);

    int tid = threadIdx.x;

    // ---- stage fp16 weights + this block's 64 perm entries ----
    for (int i = tid; i < 1024; i += TPB) {
        int k = i >> 3, j = i & 7;
        *(uint4*)(sW + k * W_STRIDE_H + j * 8) =
            *(const uint4*)(Wh + k * 64 + j * 8);
    }
    if (tid < NPB) {
        int idx = blockIdx.x * NPB + tid;
        sperm[tid] = (idx < N_NODES) ? g_perm[idx] : -1;
    }
    __syncthreads();

    // ---- gather: 8 threads/node, 8 edges/iter, weight-free HADD2 ----
    int nl = tid >> 3;                 // 0..63
    int c  = tid & 7;                  // chunk 0..7
    int node = sperm[nl];
    if (node >= 0) {
        float accf[8];
#pragma unroll
        for (int j = 0; j < 8; j++) accf[j] = 0.f;
        int e = g_off[node];
        int end = g_off[node + 1];     // end-e is a multiple of 8
        const uint4* h4 = (const uint4*)hh;

        for (; e < end; e += 8) {
            int4 Ea = *(const int4*)(g_edge + e);
            uint4 v0 = h4[(size_t)Ea.x * 8 + c];
            uint4 v1 = h4[(size_t)Ea.y * 8 + c];
            uint4 v2 = h4[(size_t)Ea.z * 8 + c];
            uint4 v3 = h4[(size_t)Ea.w * 8 + c];
            int4 Eb = *(const int4*)(g_edge + e + 4);
            half2 a0 = __hadd2(*(half2*)&v0.x, *(half2*)&v1.x);
            half2 a1 = __hadd2(*(half2*)&v0.y, *(half2*)&v1.y);
            half2 a2 = __hadd2(*(half2*)&v0.z, *(half2*)&v1.z);
            half2 a3 = __hadd2(*(half2*)&v0.w, *(half2*)&v1.w);
            HACC(a, v2);
            HACC(a, v3);
            uint4 v4 = h4[(size_t)Eb.x * 8 + c];
            uint4 v5 = h4[(size_t)Eb.y * 8 + c];
            uint4 v6 = h4[(size_t)Eb.z * 8 + c];
            uint4 v7 = h4[(size_t)Eb.w * 8 + c];
            HACC(a, v4);
            HACC(a, v5);
            HACC(a, v6);
            HACC(a, v7);
            float2 f;
            f = __half22float2(a0); accf[0] += f.x; accf[1] += f.y;
            f = __half22float2(a1); accf[2] += f.x; accf[3] += f.y;
            f = __half22float2(a2); accf[4] += f.x; accf[5] += f.y;
            f = __half22float2(a3); accf[6] += f.x; accf[7] += f.y;
        }

        // self term: x = y*sqd ; neighbor sum s = rsq*acc
        float rsq = g_rsq[node];
        float sqd = g_sqd[node];
        uint4 yv = ((const uint4*)(hh + (size_t)node * D))[c];
        float yf[8];
        cvt8(yf, yv);
        __half* row = sab + nl * AB_STRIDE_H;
        half2 pa[4], pb[4];
#pragma unroll
        for (int j = 0; j < 4; j++) {
            float x0 = yf[2*j] * sqd,      x1 = yf[2*j+1] * sqd;
            float s0 = accf[2*j] * rsq,    s1 = accf[2*j+1] * rsq;
            pa[j] = __floats2half2_rn(x0 + s0, x1 + s1);
            pb[j] = __floats2half2_rn(x0 * s0, x1 * s1);
        }
        *(uint4*)(row + 8 * c)      = *(uint4*)pa;
        *(uint4*)(row + 64 + 8 * c) = *(uint4*)pb;
    }
    __syncthreads();

    // ---- HMMA matvec ----
    int w = tid >> 5;
    int lane = tid & 31;
    int rtile = w >> 2;                // 0..3
    int cbase = (w & 3) * 2;           // ctiles cbase, cbase+1

    float d[2][4];
#pragma unroll
    for (int i = 0; i < 2; i++)
#pragma unroll
        for (int j = 0; j < 4; j++) d[i][j] = 0.f;

    unsigned a_addr = smem_u32(sab + (16 * rtile + (lane & 15)) * AB_STRIDE_H
                               + ((lane >> 4) << 3));
#pragma unroll
    for (int ks = 0; ks < 8; ks++) {
        unsigned afr[4];
        ldmatrix_x4(afr, a_addr + ks * 32);
#pragma unroll
        for (int ci = 0; ci < 2; ci++) {
            int cb = (cbase + ci) << 3;
            unsigned b_addr = smem_u32(sW + (ks * 16 + (lane & 15)) * W_STRIDE_H + cb);
            unsigned bfr[2];
            ldmatrix_x2_trans(bfr, b_addr);
            mma16816(d[ci], afr, bfr);
        }
    }

    // ---- epilogue: out = v ; next table = rsq*v ----
    int r0 = lane >> 2;
    int cc = (lane & 3) << 1;
    int node0 = sperm[16 * rtile + r0];
    int node1 = sperm[16 * rtile + r0 + 8];
    float rs0 = (houtH && node0 >= 0) ? g_rsq[node0] : 0.f;
    float rs1 = (houtH && node1 >= 0) ? g_rsq[node1] : 0.f;
#pragma unroll
    for (int ci = 0; ci < 2; ci++) {
        int col = ((cbase + ci) << 3) + cc;
        float v0 = d[ci][0], v1 = d[ci][1], v2 = d[ci][2], v3 = d[ci][3];
        if (do_relu) {
            v0 = v0 > 0.f ? v0 : NEG_SLOPE * v0;
            v1 = v1 > 0.f ? v1 : NEG_SLOPE * v1;
            v2 = v2 > 0.f ? v2 : NEG_SLOPE * v2;
            v3 = v3 > 0.f ? v3 : NEG_SLOPE * v3;
        }
        if (node0 >= 0) {
            *(float2*)(out + (size_t)node0 * 192 + colOff + col) =
                make_float2(v0, v1);
            if (houtH) {
                half2 h = __floats2half2_rn(rs0 * v0, rs0 * v1);
                *(unsigned*)(houtH + (size_t)node0 * D + col) = *(unsigned*)&h;
            }
        }
        if (node1 >= 0) {
            *(float2*)(out + (size_t)node1 * 192 + colOff + col) =
                make_float2(v2, v3);
            if (houtH) {
                half2 h = __floats2half2_rn(rs1 * v2, rs1 * v3);
                *(unsigned*)(houtH + (size_t)node1 * D + col) = *(unsigned*)&h;
            }
        }
    }
}

// ---------------- launch ----------------
extern "C" void kernel_launch(void* const* d_in, const int* in_sizes, int n_in,
                              void* d_out, int out_size) {
    const float* x   = (const float*)d_in[0];
    const float* W1a = (const float*)d_in[1];
    const float* W2a = (const float*)d_in[2];
    const float* W1b = (const float*)d_in[3];
    const float* W2b = (const float*)d_in[4];
    const int*   src = (const int*)d_in[5];
    const int*   dst = (const int*)d_in[6];
    float* out = (float*)d_out;

    __half* xh;  cudaGetSymbolAddress((void**)&xh,  g_xh);
    __half* hAh; cudaGetSymbolAddress((void**)&hAh, g_hAh);
    __half* hBh; cudaGetSymbolAddress((void**)&hBh, g_hBh);
    __half* wh;  cudaGetSymbolAddress((void**)&wh,  g_w16);
    void* degP;  cudaGetSymbolAddress(&degP, g_deg);
    void* tkP;   cudaGetSymbolAddress(&tkP, g_ticket);
    void* stP;   cudaGetSymbolAddress(&stP, g_state);
    void* hiP;   cudaGetSymbolAddress(&hiP, g_hist);

    cudaFuncSetAttribute(k_fused, cudaFuncAttributeMaxDynamicSharedMemorySize,
                         SMEM_BYTES);

    const int TB = 256;
    int gE = (N_EDGES + TB - 1) / TB;
    int gF = (N_NODES + NPB - 1) / NPB;   // 1563

    cudaMemsetAsync(degP, 0, N_NODES * sizeof(int));
    cudaMemsetAsync(tkP, 0, sizeof(int));
    cudaMemsetAsync(stP, 0, NTILES * sizeof(unsigned long long));
    cudaMemsetAsync(hiP, 0, 256 * sizeof(int));

    k_count<<<gE, TB>>>(dst);
    k_scan<<<NTILES, 256>>>();
    k_binscan<<<1, 256>>>();
    k_fill_all<<<gE, TB>>>(src, dst, x, W1a, W2a, W1b, W2b);

    k_fused<<<gF, TPB, SMEM_BYTES>>>(xh, wh,         out, hAh, 1, 0);
    k_fused<<<gF, TPB, SMEM_BYTES>>>(hAh, wh + 8192, out, hBh, 1, 64);
    k_fused<<<gF, TPB, SMEM_BYTES>>>(hBh, wh + 8192, out, (__half*)0, 0, 128);
}